// round 1
// baseline (speedup 1.0000x reference)
#include <cuda_runtime.h>
#include <cstdint>

#define BATCH 256
#define DIM   4096
#define BD    (BATCH * DIM)
#define NSTEPS 30

// Persistent scratch (device globals: allocation-free per the harness rules)
__device__ float g_s0[BD], g_s1[BD], g_s2[BD];
__device__ float g_Y0[BD], g_Y1a[BD], g_Y1b[BD], g_Y2[BD], g_top[BD];

__device__ __forceinline__ uint32_t f2tf32(float x) {
    uint32_t r;
    asm("cvt.rna.tf32.f32 %0, %1;" : "=r"(r) : "f"(x));
    return r;
}

__device__ __forceinline__ void mma8(float c[4], const uint32_t a[4], const uint32_t b[2]) {
    asm volatile(
        "mma.sync.aligned.m16n8k8.row.col.f32.tf32.tf32.f32 "
        "{%0,%1,%2,%3},{%4,%5,%6,%7},{%8,%9},{%0,%1,%2,%3};\n"
        : "+f"(c[0]), "+f"(c[1]), "+f"(c[2]), "+f"(c[3])
        : "r"(a[0]), "r"(a[1]), "r"(a[2]), "r"(a[3]), "r"(b[0]), "r"(b[1]));
}

// C[m,n] = sum_k A[m,k] * W[n,k]   (A: 256x4096 row-major, W: 4096x4096 row-major)
// mode 0: A=s3in, W=Wd, C=g_top           (single z slice)
// mode 1 (z): 0:(g_s1,Wa->g_Y0) 1:(g_s2,Wc->g_Y1a) 2:(g_s0,Wb->g_Y1b) 3:(g_s1,Wd->g_Y2)
__global__ __launch_bounds__(256) void gemm_kernel(
    int mode,
    const float* __restrict__ Wa, const float* __restrict__ Wb,
    const float* __restrict__ Wc, const float* __restrict__ Wd,
    const float* __restrict__ s3in)
{
    const float* A;
    const float* W;
    float* C;
    if (mode == 0) {
        A = s3in; W = Wd; C = g_top;
    } else {
        switch (blockIdx.z) {
            case 0:  A = g_s1; W = Wa; C = g_Y0;  break;
            case 1:  A = g_s2; W = Wc; C = g_Y1a; break;
            case 2:  A = g_s0; W = Wb; C = g_Y1b; break;
            default: A = g_s1; W = Wd; C = g_Y2;  break;
        }
    }

    // Block tile 128(M) x 128(N) x 32(K). 8 warps in 2x4; warp tile 64x32.
    __shared__ uint32_t As[128][36];   // [m][k], pad 36 (36 % 32 == 4 -> conflict-free frags)
    __shared__ uint32_t Ws[128][36];   // [n][k]

    const int tid   = threadIdx.x;
    const int warp  = tid >> 5;
    const int lane  = tid & 31;
    const int warpM = warp >> 2;       // 0..1
    const int warpN = warp & 3;        // 0..3
    const int lq    = lane >> 2;       // 0..7
    const int lr    = lane & 3;        // 0..3

    const int mBase = blockIdx.y * 128;
    const int nBase = blockIdx.x * 128;

    const int lRow = tid >> 3;         // 0..31
    const int lCol = (tid & 7) * 4;    // 0,4,...,28

    float acc[4][4][4];
    #pragma unroll
    for (int mi = 0; mi < 4; mi++)
        #pragma unroll
        for (int ni = 0; ni < 4; ni++)
            #pragma unroll
            for (int f = 0; f < 4; f++) acc[mi][ni][f] = 0.0f;

    for (int kt = 0; kt < DIM; kt += 32) {
        // Global -> SMEM (convert to tf32 once here)
        #pragma unroll
        for (int r = 0; r < 4; r++) {
            int row = r * 32 + lRow;
            float4 va = *(const float4*)(A + (size_t)(mBase + row) * DIM + kt + lCol);
            As[row][lCol + 0] = f2tf32(va.x);
            As[row][lCol + 1] = f2tf32(va.y);
            As[row][lCol + 2] = f2tf32(va.z);
            As[row][lCol + 3] = f2tf32(va.w);
            float4 vw = *(const float4*)(W + (size_t)(nBase + row) * DIM + kt + lCol);
            Ws[row][lCol + 0] = f2tf32(vw.x);
            Ws[row][lCol + 1] = f2tf32(vw.y);
            Ws[row][lCol + 2] = f2tf32(vw.z);
            Ws[row][lCol + 3] = f2tf32(vw.w);
        }
        __syncthreads();

        #pragma unroll
        for (int kk = 0; kk < 32; kk += 8) {
            uint32_t afr[4][4];
            #pragma unroll
            for (int mi = 0; mi < 4; mi++) {
                int r = warpM * 64 + mi * 16 + lq;
                afr[mi][0] = As[r    ][kk     + lr];
                afr[mi][1] = As[r + 8][kk     + lr];
                afr[mi][2] = As[r    ][kk + 4 + lr];
                afr[mi][3] = As[r + 8][kk + 4 + lr];
            }
            uint32_t bfr[4][2];
            #pragma unroll
            for (int ni = 0; ni < 4; ni++) {
                int c = warpN * 32 + ni * 8 + lq;
                bfr[ni][0] = Ws[c][kk     + lr];
                bfr[ni][1] = Ws[c][kk + 4 + lr];
            }
            #pragma unroll
            for (int mi = 0; mi < 4; mi++)
                #pragma unroll
                for (int ni = 0; ni < 4; ni++)
                    mma8(acc[mi][ni], afr[mi], bfr[ni]);
        }
        __syncthreads();
    }

    // Epilogue: scattered float2 stores
    #pragma unroll
    for (int mi = 0; mi < 4; mi++) {
        #pragma unroll
        for (int ni = 0; ni < 4; ni++) {
            int r = mBase + warpM * 64 + mi * 16 + lq;
            int c = nBase + warpN * 32 + ni * 8 + 2 * lr;
            *(float2*)(C + (size_t)r * DIM + c)       = make_float2(acc[mi][ni][0], acc[mi][ni][1]);
            *(float2*)(C + (size_t)(r + 8) * DIM + c) = make_float2(acc[mi][ni][2], acc[mi][ni][3]);
        }
    }
}

__global__ void init_kernel(const float* __restrict__ s0,
                            const float* __restrict__ s1,
                            const float* __restrict__ s2)
{
    int i = blockIdx.x * blockDim.x + threadIdx.x;
    g_s0[i] = s0[i];
    g_s1[i] = s1[i];
    g_s2[i] = s2[i];
}

__global__ void update_kernel(const float* __restrict__ b0,
                              const float* __restrict__ b2,
                              const float* __restrict__ b4)
{
    int i = blockIdx.x * blockDim.x + threadIdx.x;
    int n = i & (DIM - 1);
    float s0 = g_s0[i], s1 = g_s1[i], s2 = g_s2[i];
    // s_new = clip(0.5*s + 0.5*(input sum), 0, 1);  rho(s)==s since s in [0,1]
    float n0 = 0.5f * s0 + 0.5f * (g_Y0[i] + b0[n]);
    float n1 = 0.5f * s1 + 0.5f * (g_Y1a[i] + g_Y1b[i] + b2[n]);
    float n2 = 0.5f * s2 + 0.5f * (g_top[i] + b4[n] + g_Y2[i]);
    g_s0[i] = fminf(fmaxf(n0, 0.0f), 1.0f);
    g_s1[i] = fminf(fmaxf(n1, 0.0f), 1.0f);
    g_s2[i] = fminf(fmaxf(n2, 0.0f), 1.0f);
}

__global__ void out_kernel(float* __restrict__ out)
{
    int i = blockIdx.x * blockDim.x + threadIdx.x;
    out[i]          = g_s0[i];
    out[BD + i]     = g_s1[i];
    out[2 * BD + i] = g_s2[i];
}

extern "C" void kernel_launch(void* const* d_in, const int* in_sizes, int n_in,
                              void* d_out, int out_size)
{
    const float* s0 = (const float*)d_in[0];
    const float* s1 = (const float*)d_in[1];
    const float* s2 = (const float*)d_in[2];
    const float* s3 = (const float*)d_in[3];
    const float* W0 = (const float*)d_in[4];
    const float* b0 = (const float*)d_in[5];
    const float* W1 = (const float*)d_in[6];
    const float* W2 = (const float*)d_in[7];
    const float* b2 = (const float*)d_in[8];
    const float* W3 = (const float*)d_in[9];
    const float* W4 = (const float*)d_in[10];
    const float* b4 = (const float*)d_in[11];

    // Re-init state every call (graph replay determinism)
    init_kernel<<<BD / 256, 256>>>(s0, s1, s2);

    // top_in = s3 @ W4^T (constant across steps; b4 added in update)
    gemm_kernel<<<dim3(32, 2, 1), 256>>>(0, W0, W1, W2, W4, s3);

    for (int t = 0; t < NSTEPS; t++) {
        // All 4 GEMMs of a step read only old state -> run concurrently via z
        gemm_kernel<<<dim3(32, 2, 4), 256>>>(1, W0, W1, W2, W3, nullptr);
        update_kernel<<<BD / 256, 256>>>(b0, b2, b4);
    }

    out_kernel<<<BD / 256, 256>>>((float*)d_out);
}